// round 16
// baseline (speedup 1.0000x reference)
#include <cuda_runtime.h>
#include <math.h>

// Problem constants (fixed shapes from the reference)
#define BB 16
#define NN 512
#define HH 512
#define DD 4
#define BN (BB*NN)          // 8192
#define DH (DD*HH)          // 2048

// ---------------- scratch (device globals: allocation-free) ----------------
__device__ float g_inv[BN * DD];          // 1/(count+eps) per (row, d)
__device__ float g_agg[(size_t)BN * DH];  // 64 MB
__device__ float g_act[(size_t)BN * HH];  // 16 MB
__device__ float g_r  [(size_t)BN * HH];
__device__ float g_z  [(size_t)BN * HH];
__device__ float g_n1 [(size_t)BN * HH];
__device__ float g_n2 [(size_t)BN * HH];

// ---------------- 1) per-row direction counts -> inverse -------------------
__global__ __launch_bounds__(256) void count_kernel(const int* __restrict__ adj,
                                                    float* __restrict__ inv)
{
    int warp = (blockIdx.x * (blockDim.x >> 5)) + (threadIdx.x >> 5);
    int lane = threadIdx.x & 31;
    if (warp >= BN) return;
    const int* a = adj + (size_t)warp * NN;
    int c1 = 0, c2 = 0, c3 = 0, c4 = 0;
    for (int m = lane; m < NN; m += 32) {
        int v = a[m];
        c1 += (v == 1); c2 += (v == 2); c3 += (v == 3); c4 += (v == 4);
    }
    #pragma unroll
    for (int off = 16; off > 0; off >>= 1) {
        c1 += __shfl_down_sync(0xffffffffu, c1, off);
        c2 += __shfl_down_sync(0xffffffffu, c2, off);
        c3 += __shfl_down_sync(0xffffffffu, c3, off);
        c4 += __shfl_down_sync(0xffffffffu, c4, off);
    }
    if (lane == 0) {
        const float eps = 1e-8f;
        float4 o;
        o.x = 1.0f / ((float)c1 + eps);
        o.y = 1.0f / ((float)c2 + eps);
        o.z = 1.0f / ((float)c3 + eps);
        o.w = 1.0f / ((float)c4 + eps);
        *(float4*)&inv[warp * 4] = o;
    }
}

// ---------------- 2) masked directional aggregation -------------------------
// agg[b,n,d*H+h] = inv[b,n,d] * sum_m (adj[b,n,m]==d+1) * hid[b,m,h]
// Block: 32 n  x 64 h, all 4 directions. Threads 256: (nsub 0..15 -> rows
// nsub, nsub+16; hsub 0..15 -> 4 h each).
__global__ __launch_bounds__(256) void agg_kernel(const int* __restrict__ adj,
                                                  const float* __restrict__ hid,
                                                  const float* __restrict__ inv,
                                                  float* __restrict__ agg)
{
    const int b  = blockIdx.z;
    const int n0 = blockIdx.y * 32;
    const int h0 = blockIdx.x * 64;

    __shared__ float sMask[4][32][33];
    __shared__ float sHid[32][64];

    const int tx   = threadIdx.x;
    const int hsub = tx & 15;
    const int nsub = tx >> 4;

    float acc[2][4][4];
    #pragma unroll
    for (int a = 0; a < 2; a++)
        #pragma unroll
        for (int d = 0; d < 4; d++)
            #pragma unroll
            for (int j = 0; j < 4; j++) acc[a][d][j] = 0.0f;

    const int*   adjB = adj + ((size_t)b * NN + n0) * NN;
    const float* hidB = hid + (size_t)b * NN * HH;

    for (int m0 = 0; m0 < NN; m0 += 32) {
        // load 32x32 adj tile, expand into 4 float masks
        #pragma unroll
        for (int i = 0; i < 4; i++) {
            int lin = i * 256 + tx;
            int n = lin >> 5, m = lin & 31;
            int v = adjB[(size_t)n * NN + m0 + m];
            sMask[0][n][m] = (v == 1) ? 1.0f : 0.0f;
            sMask[1][n][m] = (v == 2) ? 1.0f : 0.0f;
            sMask[2][n][m] = (v == 3) ? 1.0f : 0.0f;
            sMask[3][n][m] = (v == 4) ? 1.0f : 0.0f;
        }
        // load 32(m) x 64(h) hid tile
        #pragma unroll
        for (int i = 0; i < 2; i++) {
            int lin = i * 256 + tx;
            int m = lin >> 4, hq = (lin & 15) << 2;
            *(float4*)&sHid[m][hq] =
                *(const float4*)&hidB[(size_t)(m0 + m) * HH + h0 + hq];
        }
        __syncthreads();

        #pragma unroll 4
        for (int mm = 0; mm < 32; mm++) {
            float4 v = *(const float4*)&sHid[mm][hsub << 2];
            #pragma unroll
            for (int d = 0; d < 4; d++) {
                float w0 = sMask[d][nsub][mm];
                float w1 = sMask[d][nsub + 16][mm];
                acc[0][d][0] += w0 * v.x;  acc[0][d][1] += w0 * v.y;
                acc[0][d][2] += w0 * v.z;  acc[0][d][3] += w0 * v.w;
                acc[1][d][0] += w1 * v.x;  acc[1][d][1] += w1 * v.y;
                acc[1][d][2] += w1 * v.z;  acc[1][d][3] += w1 * v.w;
            }
        }
        __syncthreads();
    }

    #pragma unroll
    for (int a = 0; a < 2; a++) {
        int row = b * NN + n0 + nsub + a * 16;
        #pragma unroll
        for (int d = 0; d < 4; d++) {
            float s = inv[row * 4 + d];
            float4 o;
            o.x = acc[a][d][0] * s; o.y = acc[a][d][1] * s;
            o.z = acc[a][d][2] * s; o.w = acc[a][d][3] * s;
            *(float4*)&agg[(size_t)row * DH + d * HH + h0 + (hsub << 2)] = o;
        }
    }
}

// ---------------- 3/4) generic tiled GEMM: C = A @ W^T (+bias)(+=C)(relu) ---
// A: [M,K] row-major stride lda; W: [Nc,K] row-major stride ldw.
// flags: bit0 = accumulate into existing C, bit1 = relu.
__global__ __launch_bounds__(256) void gemm_kernel(const float* __restrict__ A, int lda,
                                                   const float* __restrict__ W, int ldw,
                                                   const float* __restrict__ bias,
                                                   float* __restrict__ C, int ldc,
                                                   int K, int flags)
{
    __shared__ float sA[16][64];
    __shared__ float sW[16][64];

    const int bm = blockIdx.y * 64;
    const int bn = blockIdx.x * 64;
    const int tx = threadIdx.x;
    const int tm = tx & 15;         // C row group
    const int tn = tx >> 4;         // C col group
    const int lr = tx >> 2;         // load row (0..63)
    const int lk = (tx & 3) << 2;   // load k offset (0,4,8,12)

    float acc[4][4] = {};

    const float* Ap = A + (size_t)(bm + lr) * lda + lk;
    const float* Wp = W + (size_t)(bn + lr) * ldw + lk;

    for (int k0 = 0; k0 < K; k0 += 16) {
        float4 a4 = *(const float4*)(Ap + k0);
        float4 w4 = *(const float4*)(Wp + k0);
        sA[lk + 0][lr] = a4.x; sA[lk + 1][lr] = a4.y;
        sA[lk + 2][lr] = a4.z; sA[lk + 3][lr] = a4.w;
        sW[lk + 0][lr] = w4.x; sW[lk + 1][lr] = w4.y;
        sW[lk + 2][lr] = w4.z; sW[lk + 3][lr] = w4.w;
        __syncthreads();

        #pragma unroll
        for (int k = 0; k < 16; k++) {
            float4 av = *(const float4*)&sA[k][tm << 2];
            float4 wv = *(const float4*)&sW[k][tn << 2];
            acc[0][0] += av.x * wv.x; acc[0][1] += av.x * wv.y;
            acc[0][2] += av.x * wv.z; acc[0][3] += av.x * wv.w;
            acc[1][0] += av.y * wv.x; acc[1][1] += av.y * wv.y;
            acc[1][2] += av.y * wv.z; acc[1][3] += av.y * wv.w;
            acc[2][0] += av.z * wv.x; acc[2][1] += av.z * wv.y;
            acc[2][2] += av.z * wv.z; acc[2][3] += av.z * wv.w;
            acc[3][0] += av.w * wv.x; acc[3][1] += av.w * wv.y;
            acc[3][2] += av.w * wv.z; acc[3][3] += av.w * wv.w;
        }
        __syncthreads();
    }

    float4 bv = *(const float4*)&bias[bn + (tn << 2)];
    #pragma unroll
    for (int i = 0; i < 4; i++) {
        size_t off = (size_t)(bm + (tm << 2) + i) * ldc + bn + (tn << 2);
        float4 o;
        o.x = acc[i][0] + bv.x; o.y = acc[i][1] + bv.y;
        o.z = acc[i][2] + bv.z; o.w = acc[i][3] + bv.w;
        if (flags & 1) {
            float4 c = *(const float4*)&C[off];
            o.x += c.x; o.y += c.y; o.z += c.z; o.w += c.w;
        }
        if (flags & 2) {
            o.x = fmaxf(o.x, 0.0f); o.y = fmaxf(o.y, 0.0f);
            o.z = fmaxf(o.z, 0.0f); o.w = fmaxf(o.w, 0.0f);
        }
        *(float4*)&C[off] = o;
    }
}

// ---------------- 5) fused GRU elementwise + LayerNorm ----------------------
__device__ __forceinline__ float sigmoidf_(float x) {
    return 1.0f / (1.0f + expf(-x));
}

__global__ __launch_bounds__(128) void gru_ln_kernel(
    const float* __restrict__ R, const float* __restrict__ Z,
    const float* __restrict__ N1, const float* __restrict__ N2,
    const float* __restrict__ hid, const float* __restrict__ gamma,
    const float* __restrict__ beta, float* __restrict__ out)
{
    const int row = blockIdx.x;
    const size_t base = (size_t)row * HH;
    const int tx = threadIdx.x;
    const int h = tx << 2;

    float4 r4  = *(const float4*)&R [base + h];
    float4 z4  = *(const float4*)&Z [base + h];
    float4 n14 = *(const float4*)&N1[base + h];
    float4 n24 = *(const float4*)&N2[base + h];
    float4 h4  = *(const float4*)&hid[base + h];

    float o[4];
    {
        float rr, zz, nn;
        rr = sigmoidf_(r4.x); zz = sigmoidf_(z4.x);
        nn = tanhf(n14.x + rr * n24.x); o[0] = (1.0f - zz) * nn + zz * h4.x;
        rr = sigmoidf_(r4.y); zz = sigmoidf_(z4.y);
        nn = tanhf(n14.y + rr * n24.y); o[1] = (1.0f - zz) * nn + zz * h4.y;
        rr = sigmoidf_(r4.z); zz = sigmoidf_(z4.z);
        nn = tanhf(n14.z + rr * n24.z); o[2] = (1.0f - zz) * nn + zz * h4.z;
        rr = sigmoidf_(r4.w); zz = sigmoidf_(z4.w);
        nn = tanhf(n14.w + rr * n24.w); o[3] = (1.0f - zz) * nn + zz * h4.w;
    }

    float s = o[0] + o[1] + o[2] + o[3];
    float q = o[0]*o[0] + o[1]*o[1] + o[2]*o[2] + o[3]*o[3];
    #pragma unroll
    for (int off = 16; off > 0; off >>= 1) {
        s += __shfl_xor_sync(0xffffffffu, s, off);
        q += __shfl_xor_sync(0xffffffffu, q, off);
    }
    __shared__ float ss[4], sq[4];
    int wid = tx >> 5, lane = tx & 31;
    if (lane == 0) { ss[wid] = s; sq[wid] = q; }
    __syncthreads();
    s = ss[0] + ss[1] + ss[2] + ss[3];
    q = sq[0] + sq[1] + sq[2] + sq[3];

    float mu   = s * (1.0f / HH);
    float var  = q * (1.0f / HH) - mu * mu;
    float rstd = rsqrtf(var + 1e-5f);

    float4 g4 = *(const float4*)&gamma[h];
    float4 b4 = *(const float4*)&beta[h];
    float4 ov;
    ov.x = (o[0] - mu) * rstd * g4.x + b4.x;
    ov.y = (o[1] - mu) * rstd * g4.y + b4.y;
    ov.z = (o[2] - mu) * rstd * g4.z + b4.z;
    ov.w = (o[3] - mu) * rstd * g4.w + b4.w;
    *(float4*)&out[base + h] = ov;
}

// ---------------- launcher ---------------------------------------------------
extern "C" void kernel_launch(void* const* d_in, const int* in_sizes, int n_in,
                              void* d_out, int out_size)
{
    const int*   adj   = (const int*)  d_in[0];
    const float* hid   = (const float*)d_in[1];
    const float* Wd    = (const float*)d_in[2];
    const float* bd    = (const float*)d_in[3];
    const float* gamma = (const float*)d_in[4];
    const float* beta  = (const float*)d_in[5];
    const float* Wri = (const float*)d_in[6],  *bri = (const float*)d_in[7];
    const float* Wrh = (const float*)d_in[8],  *brh = (const float*)d_in[9];
    const float* Wzi = (const float*)d_in[10], *bzi = (const float*)d_in[11];
    const float* Wzh = (const float*)d_in[12], *bzh = (const float*)d_in[13];
    const float* Wni = (const float*)d_in[14], *bni = (const float*)d_in[15];
    const float* Wnh = (const float*)d_in[16], *bnh = (const float*)d_in[17];
    float* out = (float*)d_out;

    float *inv, *agg, *act, *bR, *bZ, *bN1, *bN2;
    cudaGetSymbolAddress((void**)&inv, g_inv);
    cudaGetSymbolAddress((void**)&agg, g_agg);
    cudaGetSymbolAddress((void**)&act, g_act);
    cudaGetSymbolAddress((void**)&bR,  g_r);
    cudaGetSymbolAddress((void**)&bZ,  g_z);
    cudaGetSymbolAddress((void**)&bN1, g_n1);
    cudaGetSymbolAddress((void**)&bN2, g_n2);

    // 1) counts
    count_kernel<<<BN / 8, 256>>>(adj, inv);

    // 2) directional aggregation -> agg [BN, 2048]
    agg_kernel<<<dim3(HH / 64, NN / 32, BB), 256>>>(adj, hid, inv, agg);

    // 3) act = relu(agg @ Wd^T + bd)   [BN, 512], K=2048
    gemm_kernel<<<dim3(HH / 64, BN / 64), 256>>>(agg, DH, Wd, DH, bd, act, HH, DH, 2);

    // 4) GRU gate GEMMs (i-path, then h-path accumulated for r/z)
    gemm_kernel<<<dim3(HH / 64, BN / 64), 256>>>(act, HH, Wri, HH, bri, bR,  HH, HH, 0);
    gemm_kernel<<<dim3(HH / 64, BN / 64), 256>>>(hid, HH, Wrh, HH, brh, bR,  HH, HH, 1);
    gemm_kernel<<<dim3(HH / 64, BN / 64), 256>>>(act, HH, Wzi, HH, bzi, bZ,  HH, HH, 0);
    gemm_kernel<<<dim3(HH / 64, BN / 64), 256>>>(hid, HH, Wzh, HH, bzh, bZ,  HH, HH, 1);
    gemm_kernel<<<dim3(HH / 64, BN / 64), 256>>>(act, HH, Wni, HH, bni, bN1, HH, HH, 0);
    gemm_kernel<<<dim3(HH / 64, BN / 64), 256>>>(hid, HH, Wnh, HH, bnh, bN2, HH, HH, 0);

    // 5) fused GRU elementwise + LayerNorm -> out
    gru_ln_kernel<<<BN, 128>>>(bR, bZ, bN1, bN2, hid, gamma, beta, out);
}

// round 17
// speedup vs baseline: 1.1648x; 1.1648x over previous
#include <cuda_runtime.h>
#include <math.h>

// Problem constants (fixed shapes from the reference)
#define BB 16
#define NN 512
#define HH 512
#define DD 4
#define BN (BB*NN)          // 8192
#define DH (DD*HH)          // 2048
#define GATES 1536          // 3*H concatenated gate width
#define TK 8                // GEMM k-tile

typedef unsigned long long ull;

// ---------------- scratch (device globals: allocation-free) ----------------
__device__ float g_inv[BN * DD];
__device__ float g_agg[(size_t)BN * DH];     // 64 MB
__device__ float g_act[(size_t)BN * HH];     // 16 MB
__device__ float g_gi [(size_t)BN * GATES];  // 48 MB
__device__ float g_gh [(size_t)BN * GATES];  // 48 MB
__device__ float g_wi [GATES * HH];
__device__ float g_wh [GATES * HH];
__device__ float g_bi [GATES];
__device__ float g_bh [GATES];

// packed f32x2 FMA: d = a*b + d (elementwise on 2 floats packed in 64 bits)
__device__ __forceinline__ void ffma2(ull& d, ull a, ull b) {
    asm volatile("fma.rn.f32x2 %0, %1, %2, %0;" : "+l"(d) : "l"(a), "l"(b));
}
__device__ __forceinline__ ull dup2(float v) {
    ull d = (ull)__float_as_uint(v);
    return d | (d << 32);
}
__device__ __forceinline__ float2 u2f(ull v) {
    float2 f;
    f.x = __uint_as_float((unsigned)v);
    f.y = __uint_as_float((unsigned)(v >> 32));
    return f;
}

// ---------------- 1) per-row direction counts -> inverse -------------------
__global__ __launch_bounds__(256) void count_kernel(const int* __restrict__ adj,
                                                    float* __restrict__ inv)
{
    int warp = (blockIdx.x * (blockDim.x >> 5)) + (threadIdx.x >> 5);
    int lane = threadIdx.x & 31;
    if (warp >= BN) return;
    const int* a = adj + (size_t)warp * NN;
    int c1 = 0, c2 = 0, c3 = 0, c4 = 0;
    for (int m = lane; m < NN; m += 32) {
        int v = a[m];
        c1 += (v == 1); c2 += (v == 2); c3 += (v == 3); c4 += (v == 4);
    }
    #pragma unroll
    for (int off = 16; off > 0; off >>= 1) {
        c1 += __shfl_down_sync(0xffffffffu, c1, off);
        c2 += __shfl_down_sync(0xffffffffu, c2, off);
        c3 += __shfl_down_sync(0xffffffffu, c3, off);
        c4 += __shfl_down_sync(0xffffffffu, c4, off);
    }
    if (lane == 0) {
        const float eps = 1e-8f;
        float4 o;
        o.x = 1.0f / ((float)c1 + eps);
        o.y = 1.0f / ((float)c2 + eps);
        o.z = 1.0f / ((float)c3 + eps);
        o.w = 1.0f / ((float)c4 + eps);
        *(float4*)&inv[warp * 4] = o;
    }
}

// ---------------- 2) masked directional aggregation (FFMA2) -----------------
// agg[b,n,d*H+h] = inv[b,n,d] * sum_m (adj[b,n,m]==d+1) * hid[b,m,h]
// Block tile: 32 n x 128 h, all 4 d. 256 threads: nsub=tid>>4 (rows nsub,
// nsub+16), hsub=tid&15 (8 h each). Masks stored duplicated {w,w} for f32x2.
__global__ __launch_bounds__(256, 2) void agg_kernel(const int* __restrict__ adj,
                                                     const float* __restrict__ hid,
                                                     const float* __restrict__ inv,
                                                     float* __restrict__ agg)
{
    const int b  = blockIdx.z;
    const int n0 = blockIdx.y * 32;
    const int h0 = blockIdx.x * 128;

    __shared__ __align__(16) ull   sMaskD[4][32][32];   // 32 KB, duplicated
    __shared__ __align__(16) float sHid[32][128];       // 16 KB

    const int tid  = threadIdx.x;
    const int hsub = tid & 15;
    const int nsub = tid >> 4;

    ull acc[2][4][4] = {};   // [row group][d][h pair]

    const int*   adjB = adj + ((size_t)b * NN + n0) * NN;
    const float* hidB = hid + (size_t)b * NN * HH;
    const ull ONE2 = 0x3F8000003F800000ULL;

    for (int m0 = 0; m0 < NN; m0 += 32) {
        // expand 32x32 adj tile into 4 duplicated masks
        #pragma unroll
        for (int i = 0; i < 4; i++) {
            int lin = i * 256 + tid;
            int n = lin >> 5, m = lin & 31;
            int v = adjB[(size_t)n * NN + m0 + m];
            sMaskD[0][n][m] = (v == 1) ? ONE2 : 0ULL;
            sMaskD[1][n][m] = (v == 2) ? ONE2 : 0ULL;
            sMaskD[2][n][m] = (v == 3) ? ONE2 : 0ULL;
            sMaskD[3][n][m] = (v == 4) ? ONE2 : 0ULL;
        }
        // load 32(m) x 128(h) hid tile
        #pragma unroll
        for (int i = 0; i < 4; i++) {
            int lin = i * 256 + tid;
            int m = lin >> 5, c4 = (lin & 31) << 2;
            *(float4*)&sHid[m][c4] =
                *(const float4*)&hidB[(size_t)(m0 + m) * HH + h0 + c4];
        }
        __syncthreads();

        #pragma unroll 2
        for (int mm = 0; mm < 32; mm++) {
            ull wm[2][4];
            #pragma unroll
            for (int d = 0; d < 4; d++) {
                wm[0][d] = sMaskD[d][nsub][mm];
                wm[1][d] = sMaskD[d][nsub + 16][mm];
            }
            ulonglong2 hv0 = *(const ulonglong2*)&sHid[mm][hsub << 3];
            ulonglong2 hv1 = *(const ulonglong2*)&sHid[mm][(hsub << 3) + 4];
            ull hp[4] = {hv0.x, hv0.y, hv1.x, hv1.y};
            #pragma unroll
            for (int a = 0; a < 2; a++)
                #pragma unroll
                for (int d = 0; d < 4; d++)
                    #pragma unroll
                    for (int p = 0; p < 4; p++)
                        ffma2(acc[a][d][p], wm[a][d], hp[p]);
        }
        __syncthreads();
    }

    #pragma unroll
    for (int a = 0; a < 2; a++) {
        int row = b * NN + n0 + nsub + a * 16;
        #pragma unroll
        for (int d = 0; d < 4; d++) {
            float s = inv[row * 4 + d];
            float2 q0 = u2f(acc[a][d][0]), q1 = u2f(acc[a][d][1]);
            float2 q2 = u2f(acc[a][d][2]), q3 = u2f(acc[a][d][3]);
            float4 o0 = {q0.x * s, q0.y * s, q1.x * s, q1.y * s};
            float4 o1 = {q2.x * s, q2.y * s, q3.x * s, q3.y * s};
            size_t base = (size_t)row * DH + d * HH + h0 + (hsub << 3);
            *(float4*)&agg[base]     = o0;
            *(float4*)&agg[base + 4] = o1;
        }
    }
}

// ---------------- 3/4) 128x128 tiled GEMM, packed f32x2 ---------------------
// C[M,Nc] = A[M,K] @ W[Nc,K]^T + bias   (relu optional)
// 256 threads, 8x8 per thread, double-buffered smem, A duplicated for FFMA2.
__global__ __launch_bounds__(256, 2) void gemm128_kernel(
    const float* __restrict__ A, int lda,
    const float* __restrict__ W, int ldw,
    const float* __restrict__ bias,
    float* __restrict__ C, int ldc,
    int K, int relu)
{
    __shared__ __align__(16) ull   sA[2][TK][128];   // {a,a} duplicated, 16 KB
    __shared__ __align__(16) float sW[2][TK][132];   // padded, 8.25 KB

    const int bm  = blockIdx.y * 128;
    const int bn  = blockIdx.x * 128;
    const int tid = threadIdx.x;
    const int tx  = tid & 15;        // n group
    const int ty  = tid >> 4;        // m group

    const int lrow = tid >> 1;       // 0..127
    const int lk   = (tid & 1) << 2; // 0 or 4

    const float* Ap = A + (size_t)(bm + lrow) * lda + lk;
    const float* Wp = W + (size_t)(bn + lrow) * ldw + lk;

    ull acc[8][4] = {};

    // prologue: tile 0 -> buf 0
    float4 a4 = *(const float4*)Ap;
    float4 w4 = *(const float4*)Wp;
    sA[0][lk + 0][lrow] = dup2(a4.x);
    sA[0][lk + 1][lrow] = dup2(a4.y);
    sA[0][lk + 2][lrow] = dup2(a4.z);
    sA[0][lk + 3][lrow] = dup2(a4.w);
    sW[0][lk + 0][lrow] = w4.x;
    sW[0][lk + 1][lrow] = w4.y;
    sW[0][lk + 2][lrow] = w4.z;
    sW[0][lk + 3][lrow] = w4.w;
    __syncthreads();

    const int T = K / TK;
    for (int t = 0; t < T; t++) {
        const int buf = t & 1;
        if (t + 1 < T) {
            a4 = *(const float4*)(Ap + (t + 1) * TK);
            w4 = *(const float4*)(Wp + (t + 1) * TK);
        }
        #pragma unroll
        for (int k = 0; k < TK; k++) {
            ulonglong2 A0 = *(const ulonglong2*)&sA[buf][k][(ty << 2)];
            ulonglong2 A1 = *(const ulonglong2*)&sA[buf][k][(ty << 2) + 2];
            ulonglong2 A2 = *(const ulonglong2*)&sA[buf][k][(ty << 2) + 64];
            ulonglong2 A3 = *(const ulonglong2*)&sA[buf][k][(ty << 2) + 66];
            ulonglong2 W0 = *(const ulonglong2*)&sW[buf][k][(tx << 2)];
            ulonglong2 W1 = *(const ulonglong2*)&sW[buf][k][(tx << 2) + 64];
            ull av[8] = {A0.x, A0.y, A1.x, A1.y, A2.x, A2.y, A3.x, A3.y};
            ull wv[4] = {W0.x, W0.y, W1.x, W1.y};
            #pragma unroll
            for (int i = 0; i < 8; i++)
                #pragma unroll
                for (int j = 0; j < 4; j++)
                    ffma2(acc[i][j], av[i], wv[j]);
        }
        if (t + 1 < T) {
            const int nb = buf ^ 1;
            sA[nb][lk + 0][lrow] = dup2(a4.x);
            sA[nb][lk + 1][lrow] = dup2(a4.y);
            sA[nb][lk + 2][lrow] = dup2(a4.z);
            sA[nb][lk + 3][lrow] = dup2(a4.w);
            sW[nb][lk + 0][lrow] = w4.x;
            sW[nb][lk + 1][lrow] = w4.y;
            sW[nb][lk + 2][lrow] = w4.z;
            sW[nb][lk + 3][lrow] = w4.w;
            __syncthreads();
        }
    }

    float4 bv0 = *(const float4*)&bias[bn + (tx << 2)];
    float4 bv1 = *(const float4*)&bias[bn + (tx << 2) + 64];
    #pragma unroll
    for (int g = 0; g < 2; g++) {
        #pragma unroll
        for (int i = 0; i < 4; i++) {
            int row = bm + (ty << 2) + i + g * 64;
            int mi = g * 4 + i;
            float2 p0 = u2f(acc[mi][0]), p1 = u2f(acc[mi][1]);
            float2 p2 = u2f(acc[mi][2]), p3 = u2f(acc[mi][3]);
            float4 o0 = {p0.x + bv0.x, p0.y + bv0.y, p1.x + bv0.z, p1.y + bv0.w};
            float4 o1 = {p2.x + bv1.x, p2.y + bv1.y, p3.x + bv1.z, p3.y + bv1.w};
            if (relu) {
                o0.x = fmaxf(o0.x, 0.f); o0.y = fmaxf(o0.y, 0.f);
                o0.z = fmaxf(o0.z, 0.f); o0.w = fmaxf(o0.w, 0.f);
                o1.x = fmaxf(o1.x, 0.f); o1.y = fmaxf(o1.y, 0.f);
                o1.z = fmaxf(o1.z, 0.f); o1.w = fmaxf(o1.w, 0.f);
            }
            size_t off = (size_t)row * ldc + bn + (tx << 2);
            *(float4*)&C[off]      = o0;
            *(float4*)&C[off + 64] = o1;
        }
    }
}

// ---------------- 5) fused GRU elementwise + LayerNorm ----------------------
__device__ __forceinline__ float sigmoidf_(float x) {
    return 1.0f / (1.0f + expf(-x));
}

__global__ __launch_bounds__(128) void gru_ln_kernel(
    const float* __restrict__ GI, const float* __restrict__ GH,
    const float* __restrict__ hid, const float* __restrict__ gamma,
    const float* __restrict__ beta, float* __restrict__ out)
{
    const int row = blockIdx.x;
    const size_t bg = (size_t)row * GATES;
    const size_t bh = (size_t)row * HH;
    const int tx = threadIdx.x;
    const int h = tx << 2;

    float4 ri = *(const float4*)&GI[bg + h];
    float4 rh = *(const float4*)&GH[bg + h];
    float4 zi = *(const float4*)&GI[bg + 512 + h];
    float4 zh = *(const float4*)&GH[bg + 512 + h];
    float4 ni = *(const float4*)&GI[bg + 1024 + h];
    float4 nh = *(const float4*)&GH[bg + 1024 + h];
    float4 h4 = *(const float4*)&hid[bh + h];

    float o[4];
    {
        float rr, zz, nn;
        rr = sigmoidf_(ri.x + rh.x); zz = sigmoidf_(zi.x + zh.x);
        nn = tanhf(ni.x + rr * nh.x); o[0] = (1.0f - zz) * nn + zz * h4.x;
        rr = sigmoidf_(ri.y + rh.y); zz = sigmoidf_(zi.y + zh.y);
        nn = tanhf(ni.y + rr * nh.y); o[1] = (1.0f - zz) * nn + zz * h4.y;
        rr = sigmoidf_(ri.z + rh.z); zz = sigmoidf_(zi.z + zh.z);
        nn = tanhf(ni.z + rr * nh.z); o[2] = (1.0f - zz) * nn + zz * h4.z;
        rr = sigmoidf_(ri.w + rh.w); zz = sigmoidf_(zi.w + zh.w);
        nn = tanhf(ni.w + rr * nh.w); o[3] = (1.0f - zz) * nn + zz * h4.w;
    }

    float s = o[0] + o[1] + o[2] + o[3];
    float q = o[0]*o[0] + o[1]*o[1] + o[2]*o[2] + o[3]*o[3];
    #pragma unroll
    for (int off = 16; off > 0; off >>= 1) {
        s += __shfl_xor_sync(0xffffffffu, s, off);
        q += __shfl_xor_sync(0xffffffffu, q, off);
    }
    __shared__ float ss[4], sq[4];
    int wid = tx >> 5, lane = tx & 31;
    if (lane == 0) { ss[wid] = s; sq[wid] = q; }
    __syncthreads();
    s = ss[0] + ss[1] + ss[2] + ss[3];
    q = sq[0] + sq[1] + sq[2] + sq[3];

    float mu   = s * (1.0f / HH);
    float var  = q * (1.0f / HH) - mu * mu;
    float rstd = rsqrtf(var + 1e-5f);

    float4 g4 = *(const float4*)&gamma[h];
    float4 b4 = *(const float4*)&beta[h];
    float4 ov;
    ov.x = (o[0] - mu) * rstd * g4.x + b4.x;
    ov.y = (o[1] - mu) * rstd * g4.y + b4.y;
    ov.z = (o[2] - mu) * rstd * g4.z + b4.z;
    ov.w = (o[3] - mu) * rstd * g4.w + b4.w;
    *(float4*)&out[bh + h] = ov;
}

// ---------------- launcher ---------------------------------------------------
extern "C" void kernel_launch(void* const* d_in, const int* in_sizes, int n_in,
                              void* d_out, int out_size)
{
    const int*   adj   = (const int*)  d_in[0];
    const float* hid   = (const float*)d_in[1];
    const float* Wd    = (const float*)d_in[2];
    const float* bd    = (const float*)d_in[3];
    const float* gamma = (const float*)d_in[4];
    const float* beta  = (const float*)d_in[5];
    const float* Wri = (const float*)d_in[6],  *bri = (const float*)d_in[7];
    const float* Wrh = (const float*)d_in[8],  *brh = (const float*)d_in[9];
    const float* Wzi = (const float*)d_in[10], *bzi = (const float*)d_in[11];
    const float* Wzh = (const float*)d_in[12], *bzh = (const float*)d_in[13];
    const float* Wni = (const float*)d_in[14], *bni = (const float*)d_in[15];
    const float* Wnh = (const float*)d_in[16], *bnh = (const float*)d_in[17];
    float* out = (float*)d_out;

    float *inv, *agg, *act, *gi, *gh, *wi, *wh, *bi, *bh;
    cudaGetSymbolAddress((void**)&inv, g_inv);
    cudaGetSymbolAddress((void**)&agg, g_agg);
    cudaGetSymbolAddress((void**)&act, g_act);
    cudaGetSymbolAddress((void**)&gi,  g_gi);
    cudaGetSymbolAddress((void**)&gh,  g_gh);
    cudaGetSymbolAddress((void**)&wi,  g_wi);
    cudaGetSymbolAddress((void**)&wh,  g_wh);
    cudaGetSymbolAddress((void**)&bi,  g_bi);
    cudaGetSymbolAddress((void**)&bh,  g_bh);

    const size_t WSZ = (size_t)HH * HH * sizeof(float);
    const size_t BSZ = (size_t)HH * sizeof(float);
    // concat gate weights/biases (captured async D2D copies)
    cudaMemcpyAsync(wi,           Wri, WSZ, cudaMemcpyDeviceToDevice, 0);
    cudaMemcpyAsync(wi + HH*HH,   Wzi, WSZ, cudaMemcpyDeviceToDevice, 0);
    cudaMemcpyAsync(wi + 2*HH*HH, Wni, WSZ, cudaMemcpyDeviceToDevice, 0);
    cudaMemcpyAsync(wh,           Wrh, WSZ, cudaMemcpyDeviceToDevice, 0);
    cudaMemcpyAsync(wh + HH*HH,   Wzh, WSZ, cudaMemcpyDeviceToDevice, 0);
    cudaMemcpyAsync(wh + 2*HH*HH, Wnh, WSZ, cudaMemcpyDeviceToDevice, 0);
    cudaMemcpyAsync(bi,           bri, BSZ, cudaMemcpyDeviceToDevice, 0);
    cudaMemcpyAsync(bi + HH,      bzi, BSZ, cudaMemcpyDeviceToDevice, 0);
    cudaMemcpyAsync(bi + 2*HH,    bni, BSZ, cudaMemcpyDeviceToDevice, 0);
    cudaMemcpyAsync(bh,           brh, BSZ, cudaMemcpyDeviceToDevice, 0);
    cudaMemcpyAsync(bh + HH,      bzh, BSZ, cudaMemcpyDeviceToDevice, 0);
    cudaMemcpyAsync(bh + 2*HH,    bnh, BSZ, cudaMemcpyDeviceToDevice, 0);

    // 1) counts
    count_kernel<<<BN / 8, 256>>>(adj, inv);

    // 2) directional aggregation -> agg [BN, 2048]  (h tile = 128 -> grid.x = 4)
    agg_kernel<<<dim3(HH / 128, NN / 32, BB), 256>>>(adj, hid, inv, agg);

    // 3) act = relu(agg @ Wd^T + bd)   [BN, 512], K=2048
    gemm128_kernel<<<dim3(HH / 128, BN / 128), 256>>>(agg, DH, Wd, DH, bd, act, HH, DH, 1);

    // 4) fused gate GEMMs (N = 1536)
    gemm128_kernel<<<dim3(GATES / 128, BN / 128), 256>>>(act, HH, wi, HH, bi, gi, GATES, HH, 0);
    gemm128_kernel<<<dim3(GATES / 128, BN / 128), 256>>>(hid, HH, wh, HH, bh, gh, GATES, HH, 0);

    // 5) fused GRU elementwise + LayerNorm -> out
    gru_ln_kernel<<<BN, 128>>>(gi, gh, hid, gamma, beta, out);
}